// round 3
// baseline (speedup 1.0000x reference)
#include <cuda_runtime.h>

// Local variance over 5x5 window, reflect padding.
// Input: image float32 [16,3,1024,1024]; patch_size=5 (hardcoded, verified vs metadata).
// Output: float32 same shape.

#define TILE 32
#define HALO 2
#define STILE (TILE + 2 * HALO)   // 36
#define IMG_H 1024
#define IMG_W 1024
#define NPLANES 48                // 16 * 3

__device__ __forceinline__ int reflect_idx(int i, int n) {
    // jnp.pad(..., mode="reflect"): no edge repeat
    if (i < 0) i = -i;
    if (i >= n) i = 2 * (n - 1) - i;
    return i;
}

__global__ __launch_bounds__(256, 4)
void locvar5_kernel(const float* __restrict__ in, float* __restrict__ out) {
    __shared__ float sx[STILE][STILE + 1];   // +1 pad: avoids any column-access conflicts
    __shared__ float vs[TILE][STILE + 1];
    __shared__ float vs2[TILE][STILE + 1];

    const int plane = blockIdx.z;
    const float* __restrict__ src = in + (size_t)plane * IMG_H * IMG_W;
    float* __restrict__ dst = out + (size_t)plane * IMG_H * IMG_W;

    const int bx = blockIdx.x * TILE;
    const int by = blockIdx.y * TILE;
    const int tid = threadIdx.y * 32 + threadIdx.x;

    // ---- Load 36x36 halo tile (reflect-padded) ----
    #pragma unroll
    for (int i = tid; i < STILE * STILE; i += 256) {
        const int ly = i / STILE;
        const int lx = i - ly * STILE;
        const int gy = reflect_idx(by + ly - HALO, IMG_H);
        const int gx = reflect_idx(bx + lx - HALO, IMG_W);
        sx[ly][lx] = src[gy * IMG_W + gx];
    }
    __syncthreads();

    // ---- Vertical 5-sums of x and x^2: rows [0,TILE), cols [0,STILE) ----
    #pragma unroll
    for (int i = tid; i < TILE * STILE; i += 256) {
        const int r = i / STILE;
        const int c = i - r * STILE;
        float s = 0.f, s2 = 0.f;
        #pragma unroll
        for (int k = 0; k < 5; k++) {
            const float v = sx[r + k][c];
            s  += v;
            s2 += v * v;
        }
        vs[r][c]  = s;
        vs2[r][c] = s2;
    }
    __syncthreads();

    // ---- Horizontal 5-sums + variance, write out ----
    const int tx = threadIdx.x;
    const float inv_n = 1.0f / 25.0f;
    #pragma unroll
    for (int r = threadIdx.y; r < TILE; r += 8) {
        float s = 0.f, s2 = 0.f;
        #pragma unroll
        for (int k = 0; k < 5; k++) {
            s  += vs[r][tx + k];
            s2 += vs2[r][tx + k];
        }
        const float m = s * inv_n;
        dst[(size_t)(by + r) * IMG_W + (bx + tx)] = fmaf(-m, m, s2 * inv_n);
    }
}

extern "C" void kernel_launch(void* const* d_in, const int* in_sizes, int n_in,
                              void* d_out, int out_size) {
    const float* in = (const float*)d_in[0];
    float* out = (float*)d_out;
    dim3 grid(IMG_W / TILE, IMG_H / TILE, NPLANES);
    dim3 block(32, 8);
    locvar5_kernel<<<grid, block>>>(in, out);
}

// round 4
// speedup vs baseline: 1.4736x; 1.4736x over previous
#include <cuda_runtime.h>

// Local 5x5 variance, reflect padding. float32 [16,3,1024,1024] -> same shape.
//
// Strategy: 64(w) x 128(h) output tile per 256-thread CTA.
//   Stage A: reflect-padded 132x72 float tile staged into smem via float4.
//   Stage B: each thread owns 4 cols x 8 rows. Per x-row: 3x LDS.128,
//            horizontal 5-sums of x and x^2 in registers (incremental),
//            5-row register ring for the vertical 5-sum, float4 STG per row.

#define IMG 1024
#define NPLANES 48
#define TW 64
#define TH 128
#define SROWS (TH + 4)       // 132
#define SCOL4 18             // 18 float4 = 72 floats per smem row
#define THREADS 256

__device__ __forceinline__ int reflect_idx(int i, int n) {
    if (i < 0) i = -i;
    if (i >= n) i = 2 * (n - 1) - i;
    return i;
}

// Horizontal 5-sums of x and x^2 for 4 consecutive output columns.
// p points at float4 index [srow][tx4]; loaded scols cover c..c+11,
// needed x are at float indices 2..9 of that window.
__device__ __forceinline__ void rowsum(const float4* __restrict__ p,
                                       float* __restrict__ hh,
                                       float* __restrict__ hh2) {
    const float4 a = p[0];
    const float4 b = p[1];
    const float4 c = p[2];
    float x0 = a.z, x1 = a.w, x2 = b.x, x3 = b.y;
    float x4 = b.z, x5 = b.w, x6 = c.x, x7 = c.y;

    float h0 = x0 + x1 + x2 + x3 + x4;
    hh[0] = h0;
    hh[1] = h0    - x0 + x5;
    hh[2] = hh[1] - x1 + x6;
    hh[3] = hh[2] - x2 + x7;

    float q0 = x0 * x0, q1 = x1 * x1, q2 = x2 * x2, q3 = x3 * x3;
    float q4 = x4 * x4, q5 = x5 * x5, q6 = x6 * x6, q7 = x7 * x7;
    float g0 = q0 + q1 + q2 + q3 + q4;
    hh2[0] = g0;
    hh2[1] = g0     - q0 + q5;
    hh2[2] = hh2[1] - q1 + q6;
    hh2[3] = hh2[2] - q2 + q7;
}

__global__ __launch_bounds__(THREADS, 3)
void locvar5_kernel(const float* __restrict__ in, float* __restrict__ out) {
    __shared__ float4 sx4[SROWS * SCOL4];

    const int plane = blockIdx.z;
    const float* __restrict__ src = in + (size_t)plane * IMG * IMG;
    float* __restrict__ dst = out + (size_t)plane * IMG * IMG;

    const int bx = blockIdx.x * TW;
    const int by = blockIdx.y * TH;
    const int tid = threadIdx.x;

    // ---- Stage A: stage reflect-padded 132 x 72 tile (float cols bx-4 .. bx+67) ----
    const bool colEdge = (bx == 0) || (bx + TW == IMG);
    #pragma unroll 2
    for (int i = tid; i < SROWS * SCOL4; i += THREADS) {
        const int row = i / SCOL4;
        const int c4  = i - row * SCOL4;
        const int gy  = reflect_idx(by + row - 2, IMG);
        const int gxb = bx - 4 + c4 * 4;
        if (!colEdge) {
            sx4[i] = *(const float4*)(src + (size_t)gy * IMG + gxb);
        } else {
            float4 v;
            v.x = src[(size_t)gy * IMG + reflect_idx(gxb + 0, IMG)];
            v.y = src[(size_t)gy * IMG + reflect_idx(gxb + 1, IMG)];
            v.z = src[(size_t)gy * IMG + reflect_idx(gxb + 2, IMG)];
            v.w = src[(size_t)gy * IMG + reflect_idx(gxb + 3, IMG)];
            sx4[i] = v;
        }
    }
    __syncthreads();

    // ---- Stage B: register-ring separable sums ----
    const int tx4 = tid & 15;        // 16 col-strips of 4 output columns
    const int ty  = tid >> 4;        // 16 row-strips of 8 output rows
    const int r0  = ty * 8;          // first output row (tile-relative)

    // thread's smem window: float4 [r0 + j][tx4 .. tx4+2], j = 0..11
    const float4* sp = sx4 + r0 * SCOL4 + tx4;

    float h[5][4], h2[5][4];

    #pragma unroll
    for (int j = 0; j < 4; ++j)
        rowsum(sp + j * SCOL4, h[j], h2[j]);

    float4* op = (float4*)(dst + (size_t)(by + r0) * IMG + bx + tx4 * 4);
    const float inv_n = 1.0f / 25.0f;

    #pragma unroll
    for (int j = 4; j < 12; ++j) {
        rowsum(sp + j * SCOL4, h[j % 5], h2[j % 5]);

        float4 o;
        float* po = (float*)&o;
        #pragma unroll
        for (int c = 0; c < 4; ++c) {
            const float S = h[0][c] + h[1][c] + h[2][c] + h[3][c] + h[4][c];
            const float T = h2[0][c] + h2[1][c] + h2[2][c] + h2[3][c] + h2[4][c];
            const float m = S * inv_n;
            po[c] = fmaf(-m, m, T * inv_n);
        }
        *op = o;
        op += IMG / 4;
    }
}

extern "C" void kernel_launch(void* const* d_in, const int* in_sizes, int n_in,
                              void* d_out, int out_size) {
    const float* in = (const float*)d_in[0];
    float* out = (float*)d_out;
    dim3 grid(IMG / TW, IMG / TH, NPLANES);
    locvar5_kernel<<<grid, THREADS>>>(in, out);
}